// round 13
// baseline (speedup 1.0000x reference)
#include <cuda_runtime.h>
#include <cuda_fp16.h>
#include <cstdint>
#include <math.h>

// Problem constants
#define Bn   2
#define Tn   2048
#define Cn   2048
#define NH   16
#define NKV  4
#define HD   128
#define REP  (NH / NKV)          // 4
#define Mrows (Bn * Tn)          // 4096
#define KVC  (NKV * HD)          // 512

// ===========================================================================
// Scratch (device globals; no runtime allocation allowed)
// ===========================================================================
__device__ __half g_X16[(size_t)Mrows * Cn];
__device__ __half g_Q16[(size_t)Mrows * Cn];
__device__ __half g_K16[(size_t)Mrows * KVC];
__device__ __half g_V16[(size_t)Mrows * KVC];
__device__ __half g_Y16[(size_t)Mrows * Cn];

// transposed weights [N][K] (K-major) fp16
__device__ __half g_WqT[(size_t)Cn * Cn];
__device__ __half g_WkT[(size_t)KVC * Cn];
__device__ __half g_WvT[(size_t)KVC * Cn];
__device__ __half g_WoT[(size_t)Cn * Cn];

// ===========================================================================
// PTX helpers
// ===========================================================================
__device__ __forceinline__ uint32_t smem_u32(const void* p) {
    uint32_t a;
    asm("{ .reg .u64 t; cvta.to.shared.u64 t, %1; cvt.u32.u64 %0, t; }"
        : "=r"(a) : "l"(p));
    return a;
}
__device__ __forceinline__ void cp_async16(uint32_t dst, const void* src) {
    asm volatile("cp.async.cg.shared.global [%0], [%1], 16;"
                 :: "r"(dst), "l"(src) : "memory");
}
__device__ __forceinline__ void cp_commit() {
    asm volatile("cp.async.commit_group;" ::: "memory");
}
template <int N> __device__ __forceinline__ void cp_wait_group() {
    asm volatile("cp.async.wait_group %0;" :: "n"(N) : "memory");
}
__device__ __forceinline__ void ldsm_x4(uint32_t* r, uint32_t addr) {
    asm volatile("ldmatrix.sync.aligned.m8n8.x4.shared.b16 {%0,%1,%2,%3}, [%4];"
                 : "=r"(r[0]), "=r"(r[1]), "=r"(r[2]), "=r"(r[3]) : "r"(addr));
}
__device__ __forceinline__ void ldsm_x4_t(uint32_t* r, uint32_t addr) {
    asm volatile("ldmatrix.sync.aligned.m8n8.x4.trans.shared.b16 {%0,%1,%2,%3}, [%4];"
                 : "=r"(r[0]), "=r"(r[1]), "=r"(r[2]), "=r"(r[3]) : "r"(addr));
}
__device__ __forceinline__ void mma16816(float* c, const uint32_t* a, const uint32_t* b) {
    asm volatile(
        "mma.sync.aligned.m16n8k16.row.col.f32.f16.f16.f32 "
        "{%0,%1,%2,%3}, {%4,%5,%6,%7}, {%8,%9}, {%0,%1,%2,%3};"
        : "+f"(c[0]), "+f"(c[1]), "+f"(c[2]), "+f"(c[3])
        : "r"(a[0]), "r"(a[1]), "r"(a[2]), "r"(a[3]), "r"(b[0]), "r"(b[1]));
}
__device__ __forceinline__ uint32_t pack_h2(float a, float b) {
    __half2 t = __floats2half2_rn(a, b);
    return *(uint32_t*)&t;
}

// ===========================================================================
// Fused prep: z = 0..3 -> transpose+convert Wq/Wk/Wv/Wo;  z = 4 -> convert X
// grid (128, 64, 5)
// ===========================================================================
__global__ __launch_bounds__(256)
void prep_kernel(const float* __restrict__ x,
                 const float* __restrict__ Wq, const float* __restrict__ Wk,
                 const float* __restrict__ Wv, const float* __restrict__ Wo,
                 __half* __restrict__ X16,
                 __half* __restrict__ WqT, __half* __restrict__ WkT,
                 __half* __restrict__ WvT, __half* __restrict__ WoT)
{
    const int z = blockIdx.z;
    if (z == 4) {
        int i = (blockIdx.y * gridDim.x + blockIdx.x) * 256 + threadIdx.x;
        int total4 = (Mrows * Cn) / 4;   // 2M
        if (i < total4) {
            float4 v = ((const float4*)x)[i];
            ((__half2*)X16)[2 * i]     = __floats2half2_rn(v.x, v.y);
            ((__half2*)X16)[2 * i + 1] = __floats2half2_rn(v.z, v.w);
        }
        return;
    }
    const float* W;
    __half* T;
    int N;
    if (z == 0)      { W = Wq; T = WqT; N = Cn; }
    else if (z == 1) { W = Wk; T = WkT; N = KVC; }
    else if (z == 2) { W = Wv; T = WvT; N = KVC; }
    else             { W = Wo; T = WoT; N = Cn; }
    const int K = Cn;
    int n0 = blockIdx.x * 32, k0 = blockIdx.y * 32;
    if (n0 >= N) return;

    __shared__ float tile[32][33];
    int tx = threadIdx.x & 31, ty = threadIdx.x >> 5;
#pragma unroll
    for (int i = 0; i < 32; i += 8)
        tile[ty + i][tx] = W[(size_t)(k0 + ty + i) * N + n0 + tx];
    __syncthreads();
#pragma unroll
    for (int i = 0; i < 32; i += 8)
        T[(size_t)(n0 + ty + i) * K + k0 + tx] = __float2half(tile[tx][ty + i]);
}

// ===========================================================================
// fp16 HMMA GEMM: C[M,N] = A @ B^T (fp32 acc)
// 128x128 CTA tile, BK=64, 128 threads / 4 warps (2x2), 64x64 warp tiles,
// 2-stage cp.async pipeline; prefetch spread across kk steps; hoisted ptrs.
// MODE 0: fp32 out. MODE 1: fp16 out. MODE 2: rope + fp16 out.
// MODE 3: rope + attn-scale + fp16 out (for Q).
// ===========================================================================
#define TBK 64
#define RS  72                            // 64 + 8 pad (halves)
#define MAT_BYTES (128 * RS * 2)          // 18432
#define STG_BYTES (2 * MAT_BYTES)         // 36864
#define GEMM_SMEM (2 * STG_BYTES)         // 73728

#define SSCALE 0.08838834764831845f      // 1/sqrt(128)

template <int MODE>
__device__ __forceinline__ void gemm_core(
    const __half* __restrict__ A, const __half* __restrict__ B,
    float* __restrict__ Cf, __half* __restrict__ Ch,
    int ldc, int K,
    const float* __restrict__ fcos, const float* __restrict__ fsin, int rowg0)
{
    extern __shared__ char smem[];
    const uint32_t sb = smem_u32(smem);
    const int tid = threadIdx.x;
    const int lane = tid & 31;
    const int wid = tid >> 5;        // 0..3
    const int wm = wid & 1;
    const int wn = wid >> 1;

    float acc[4][8][4];
#pragma unroll
    for (int i = 0; i < 4; i++)
#pragma unroll
        for (int j = 0; j < 8; j++)
#pragma unroll
            for (int q = 0; q < 4; q++) acc[i][j][q] = 0.f;

    const int a_row_in = (lane & 15);
    const int a_koff   = (lane >> 4) * 8;
    const int b_row_in = (lane & 7) + ((lane >> 4) * 8);
    const int b_koff   = ((lane >> 3) & 1) * 8;

    // hoisted per-thread cp.async addressing
    const int ld_r0  = tid >> 3;
    const int ld_seg = tid & 7;
    const __half* Aptr[8];
    const __half* Bptr[8];
    uint32_t soff[8];
#pragma unroll
    for (int j = 0; j < 8; j++) {
        int r = ld_r0 + j * 16;
        soff[j] = (uint32_t)(r * (RS * 2) + ld_seg * 16);
        Aptr[j] = A + (size_t)r * K + ld_seg * 8;
        Bptr[j] = B + (size_t)r * K + ld_seg * 8;
    }

    const int NC = K / TBK;
    {
        uint32_t st = sb;
#pragma unroll
        for (int j = 0; j < 8; j++) {
            cp_async16(st + soff[j],             Aptr[j]);
            cp_async16(st + MAT_BYTES + soff[j], Bptr[j]);
            Aptr[j] += TBK; Bptr[j] += TBK;
        }
        cp_commit();
    }

    for (int c = 0; c < NC; c++) {
        cp_wait_group<0>();
        __syncthreads();

        const uint32_t st = sb + (c & 1) * STG_BYTES;
        const uint32_t stn = sb + ((c + 1) & 1) * STG_BYTES;
        const bool pf = (c + 1 < NC);

#pragma unroll
        for (int kk = 0; kk < 4; kk++) {
            const int k0 = kk * 16;
            uint32_t af[4][4];
#pragma unroll
            for (int mt = 0; mt < 4; mt++) {
                int row = wm * 64 + mt * 16 + a_row_in;
                ldsm_x4(af[mt], st + (uint32_t)(row * (RS * 2) + (k0 + a_koff) * 2));
            }
            uint32_t bf[4][4];
#pragma unroll
            for (int nt = 0; nt < 4; nt++) {
                int rowb = wn * 64 + nt * 16 + b_row_in;
                ldsm_x4(bf[nt], st + MAT_BYTES
                        + (uint32_t)(rowb * (RS * 2) + (k0 + b_koff) * 2));
            }
            if (pf) {
#pragma unroll
                for (int j = 2 * kk; j < 2 * kk + 2; j++) {
                    cp_async16(stn + soff[j],             Aptr[j]);
                    cp_async16(stn + MAT_BYTES + soff[j], Bptr[j]);
                    Aptr[j] += TBK; Bptr[j] += TBK;
                }
            }
#pragma unroll
            for (int mt = 0; mt < 4; mt++)
#pragma unroll
                for (int nt = 0; nt < 4; nt++) {
                    mma16816(acc[mt][2 * nt],     af[mt], bf[nt]);
                    mma16816(acc[mt][2 * nt + 1], af[mt], bf[nt] + 2);
                }
        }
        if (pf) cp_commit();
    }

#pragma unroll
    for (int mt = 0; mt < 4; mt++) {
#pragma unroll
        for (int nt = 0; nt < 8; nt++) {
            int row = wm * 64 + mt * 16 + (lane >> 2);
            int col = wn * 64 + nt * 8 + (lane & 3) * 2;
            float v0 = acc[mt][nt][0], v1 = acc[mt][nt][1];
            float v2 = acc[mt][nt][2], v3 = acc[mt][nt][3];
            if (MODE == 0) {
                *(float2*)(Cf + (size_t)row * ldc + col) = make_float2(v0, v1);
                *(float2*)(Cf + (size_t)(row + 8) * ldc + col) = make_float2(v2, v3);
            } else {
                if (MODE >= 2) {
                    int i = (col & 127) >> 1;
                    int t1 = (rowg0 + row) & (Tn - 1);
                    int t2 = (rowg0 + row + 8) & (Tn - 1);
                    float c1 = fcos[t1 * 64 + i], s1 = fsin[t1 * 64 + i];
                    float c2 = fcos[t2 * 64 + i], s2 = fsin[t2 * 64 + i];
                    float re = v0, im = v1;
                    v0 = re * c1 - im * s1; v1 = re * s1 + im * c1;
                    re = v2; im = v3;
                    v2 = re * c2 - im * s2; v3 = re * s2 + im * c2;
                    if (MODE == 3) {
                        v0 *= SSCALE; v1 *= SSCALE; v2 *= SSCALE; v3 *= SSCALE;
                    }
                }
                *(__half2*)(Ch + (size_t)row * ldc + col) = __floats2half2_rn(v0, v1);
                *(__half2*)(Ch + (size_t)(row + 8) * ldc + col) = __floats2half2_rn(v2, v3);
            }
        }
    }
}

// Fused QKV projection: grid (24, 32). Col tiles 0-15 -> Q (rope+scale),
// 16-19 -> K (rope), 20-23 -> V
__global__ __launch_bounds__(128)
void gemm_qkv(const __half* __restrict__ X16,
              const __half* __restrict__ WqT, const __half* __restrict__ WkT,
              const __half* __restrict__ WvT,
              __half* __restrict__ Q, __half* __restrict__ Ko, __half* __restrict__ Vo,
              const float* __restrict__ fcos, const float* __restrict__ fsin)
{
    const int ct = blockIdx.x;
    const int row0 = blockIdx.y * 128;
    const __half* Xp = X16 + (size_t)row0 * Cn;
    if (ct < 16) {
        int c0 = ct * 128;
        gemm_core<3>(Xp, WqT + (size_t)c0 * Cn, nullptr,
                     Q + (size_t)row0 * Cn + c0, Cn, Cn, fcos, fsin, row0);
    } else if (ct < 20) {
        int c0 = (ct - 16) * 128;
        gemm_core<2>(Xp, WkT + (size_t)c0 * Cn, nullptr,
                     Ko + (size_t)row0 * KVC + c0, KVC, Cn, fcos, fsin, row0);
    } else {
        int c0 = (ct - 20) * 128;
        gemm_core<1>(Xp, WvT + (size_t)c0 * Cn, nullptr,
                     Vo + (size_t)row0 * KVC + c0, KVC, Cn, nullptr, nullptr, row0);
    }
}

// Output projection GEMM (fp32 out)
__global__ __launch_bounds__(128)
void gemm_out(const __half* __restrict__ A, const __half* __restrict__ B,
              float* __restrict__ C, int N, int K)
{
    const int row0 = blockIdx.y * 128;
    const int col0 = blockIdx.x * 128;
    gemm_core<0>(A + (size_t)row0 * K, B + (size_t)col0 * K,
                 C + (size_t)row0 * N + col0, nullptr,
                 N, K, nullptr, nullptr, 0);
}

// ===========================================================================
// Flash attention on fp16 HMMA (causal, GQA)
// Q pre-scaled by 1/sqrt(d) in the QKV epilogue; hoisted load pointers.
// ===========================================================================
#define FST 136
#define FROWB (FST * 2)              // 272 bytes per row
#define QTILE_B (128 * FROWB)        // 34816
#define KTILE_B (64 * FROWB)         // 17408
#define KVSTG_B (2 * KTILE_B)        // 34816 per stage (K+V)
#define FLASH_SMEM (QTILE_B + 2 * KVSTG_B)   // 104448

__global__ __launch_bounds__(256)
void flash_attn_mma(const __half* __restrict__ Qg, const __half* __restrict__ Kg,
                    const __half* __restrict__ Vg, __half* __restrict__ Yg)
{
    extern __shared__ char smc[];
    const uint32_t sb  = smem_u32(smc);
    const uint32_t sQ  = sb;
    const uint32_t sKV0 = sb + QTILE_B;

    const int tid = threadIdx.x;
    const int lane = tid & 31;
    const int w = tid >> 5;
    const int bq = gridDim.x - 1 - blockIdx.x;       // heavy blocks first
    const int h = blockIdx.y, b = blockIdx.z;
    const int q0 = bq * 128;
    const int kvh = h / REP;

    const __half* Qp = Qg + ((size_t)b * Tn + q0) * Cn + h * HD;

    // hoisted per-thread K/V load pointers: thread owns 4 rows (r = tid>>4 + 16i)
    const int f_r0  = tid >> 4;
    const int f_seg = tid & 15;
    const __half* Kcur[4];
    const __half* Vcur[4];
    uint32_t foff[4];
    {
        const __half* Kb = Kg + (size_t)b * Tn * KVC + kvh * HD + f_seg * 8;
        const __half* Vb = Vg + (size_t)b * Tn * KVC + kvh * HD + f_seg * 8;
#pragma unroll
        for (int i = 0; i < 4; i++) {
            int r = f_r0 + i * 16;
            foff[i] = (uint32_t)(r * FROWB + f_seg * 16);
            Kcur[i] = Kb + (size_t)r * KVC;
            Vcur[i] = Vb + (size_t)r * KVC;
        }
    }

    // Q tile loads + KV tile 0 (one commit group)
#pragma unroll
    for (int i = 0; i < 8; i++) {
        int idx = tid + i * 256;
        int r = idx >> 4, seg = idx & 15;
        uint32_t off = (uint32_t)(r * FROWB + seg * 16);
        cp_async16(sQ + off, Qp + (size_t)r * Cn + seg * 8);
    }
#pragma unroll
    for (int i = 0; i < 4; i++) {
        cp_async16(sKV0 + foff[i],           Kcur[i]);
        cp_async16(sKV0 + KTILE_B + foff[i], Vcur[i]);
        Kcur[i] += 64 * KVC; Vcur[i] += 64 * KVC;
    }
    cp_commit();

    const int arow = lane & 15;
    const int akoff = (lane >> 4) * 8;
    const int brow = (lane & 7) + ((lane >> 4) * 8);
    const int bkoff = ((lane >> 3) & 1) * 8;
    const int vrow = lane & 15;
    const int vnoff = (lane >> 4) * 8;

    float Oa[16][4];
#pragma unroll
    for (int i = 0; i < 16; i++)
#pragma unroll
        for (int q = 0; q < 4; q++) Oa[i][q] = 0.f;

    float m1 = -1e30f, m2 = -1e30f, l1 = 0.f, l2 = 0.f;
    const int rg1 = q0 + w * 16 + (lane >> 2);
    const int rg2 = rg1 + 8;

    const int nkb = 2 * bq + 2;
    for (int j = 0; j < nkb; j++) {
        const int k0g = j * 64;
        const uint32_t skv = sKV0 + (j & 1) * KVSTG_B;
        if (j + 1 < nkb) {
            const uint32_t skn = sKV0 + ((j + 1) & 1) * KVSTG_B;
#pragma unroll
            for (int i = 0; i < 4; i++) {
                cp_async16(skn + foff[i],           Kcur[i]);
                cp_async16(skn + KTILE_B + foff[i], Vcur[i]);
                Kcur[i] += 64 * KVC; Vcur[i] += 64 * KVC;
            }
            cp_commit();
            cp_wait_group<1>();
        } else {
            cp_wait_group<0>();
        }
        __syncthreads();

        const uint32_t sK = skv;
        const uint32_t sV = skv + KTILE_B;

        float S[8][4];
#pragma unroll
        for (int t = 0; t < 8; t++)
#pragma unroll
            for (int q = 0; q < 4; q++) S[t][q] = 0.f;

#pragma unroll
        for (int kc = 0; kc < 8; kc++) {
            uint32_t af[4];
            ldsm_x4(af, sQ + (uint32_t)((w * 16 + arow) * FROWB + (kc * 16 + akoff) * 2));
#pragma unroll
            for (int np = 0; np < 4; np++) {
                uint32_t bf[4];
                ldsm_x4(bf, sK + (uint32_t)((np * 16 + brow) * FROWB + (kc * 16 + bkoff) * 2));
                mma16816(S[2 * np],     af, bf);
                mma16816(S[2 * np + 1], af, bf + 2);
            }
        }

        // mask + online softmax (Q pre-scaled; S is already scaled)
        const bool diag = (k0g + 63 > q0 + w * 16);
        float mx1 = -1e30f, mx2 = -1e30f;
#pragma unroll
        for (int t = 0; t < 8; t++) {
            int cg = k0g + t * 8 + (lane & 3) * 2;
#pragma unroll
            for (int e = 0; e < 2; e++) {
                float s0 = S[t][e];
                float s1 = S[t][2 + e];
                if (diag) {
                    if (cg + e > rg1) s0 = -1e30f;
                    if (cg + e > rg2) s1 = -1e30f;
                }
                S[t][e] = s0;
                S[t][2 + e] = s1;
                mx1 = fmaxf(mx1, s0);
                mx2 = fmaxf(mx2, s1);
            }
        }
        mx1 = fmaxf(mx1, __shfl_xor_sync(0xffffffff, mx1, 1));
        mx1 = fmaxf(mx1, __shfl_xor_sync(0xffffffff, mx1, 2));
        mx2 = fmaxf(mx2, __shfl_xor_sync(0xffffffff, mx2, 1));
        mx2 = fmaxf(mx2, __shfl_xor_sync(0xffffffff, mx2, 2));

        float mn1 = fmaxf(m1, mx1), mn2 = fmaxf(m2, mx2);
        float f1 = __expf(m1 - mn1), f2 = __expf(m2 - mn2);
        float rs1 = 0.f, rs2 = 0.f;
#pragma unroll
        for (int t = 0; t < 8; t++) {
#pragma unroll
            for (int e = 0; e < 2; e++) {
                float p0 = __expf(S[t][e] - mn1);
                float p1 = __expf(S[t][2 + e] - mn2);
                S[t][e] = p0;
                S[t][2 + e] = p1;
                rs1 += p0;
                rs2 += p1;
            }
        }
        rs1 += __shfl_xor_sync(0xffffffff, rs1, 1);
        rs1 += __shfl_xor_sync(0xffffffff, rs1, 2);
        rs2 += __shfl_xor_sync(0xffffffff, rs2, 1);
        rs2 += __shfl_xor_sync(0xffffffff, rs2, 2);
        l1 = l1 * f1 + rs1;
        l2 = l2 * f2 + rs2;
        m1 = mn1; m2 = mn2;
#pragma unroll
        for (int t = 0; t < 16; t++) {
            Oa[t][0] *= f1; Oa[t][1] *= f1;
            Oa[t][2] *= f2; Oa[t][3] *= f2;
        }

#pragma unroll
        for (int kc = 0; kc < 4; kc++) {
            uint32_t pf[4];
            pf[0] = pack_h2(S[2 * kc][0],     S[2 * kc][1]);
            pf[1] = pack_h2(S[2 * kc][2],     S[2 * kc][3]);
            pf[2] = pack_h2(S[2 * kc + 1][0], S[2 * kc + 1][1]);
            pf[3] = pack_h2(S[2 * kc + 1][2], S[2 * kc + 1][3]);
#pragma unroll
            for (int np = 0; np < 8; np++) {
                uint32_t vf[4];
                ldsm_x4_t(vf, sV + (uint32_t)((kc * 16 + vrow) * FROWB
                                              + (np * 16 + vnoff) * 2));
                mma16816(Oa[2 * np],     pf, vf);
                mma16816(Oa[2 * np + 1], pf, vf + 2);
            }
        }
        __syncthreads();
    }

    const float il1 = 1.f / l1, il2 = 1.f / l2;
    const size_t base1 = ((size_t)b * Tn + q0 + w * 16 + (lane >> 2)) * Cn + h * HD;
    const size_t base2 = base1 + 8 * (size_t)Cn;
#pragma unroll
    for (int nt = 0; nt < 16; nt++) {
        int col = nt * 8 + (lane & 3) * 2;
        *(__half2*)(Yg + base1 + col) =
            __floats2half2_rn(Oa[nt][0] * il1, Oa[nt][1] * il1);
        *(__half2*)(Yg + base2 + col) =
            __floats2half2_rn(Oa[nt][2] * il2, Oa[nt][3] * il2);
    }
}

// ===========================================================================
// launch
// ===========================================================================
extern "C" void kernel_launch(void* const* d_in, const int* in_sizes, int n_in,
                              void* d_out, int out_size)
{
    const float* x   = (const float*)d_in[0];
    const float* Wq  = (const float*)d_in[1];
    const float* Wk  = (const float*)d_in[2];
    const float* Wv  = (const float*)d_in[3];
    const float* Wo  = (const float*)d_in[4];
    const float* fc  = (const float*)d_in[5];
    const float* fs  = (const float*)d_in[6];
    float* out = (float*)d_out;

    __half *X16, *Q16, *K16, *V16, *Y16, *WqT, *WkT, *WvT, *WoT;
    cudaGetSymbolAddress((void**)&X16, g_X16);
    cudaGetSymbolAddress((void**)&Q16, g_Q16);
    cudaGetSymbolAddress((void**)&K16, g_K16);
    cudaGetSymbolAddress((void**)&V16, g_V16);
    cudaGetSymbolAddress((void**)&Y16, g_Y16);
    cudaGetSymbolAddress((void**)&WqT, g_WqT);
    cudaGetSymbolAddress((void**)&WkT, g_WkT);
    cudaGetSymbolAddress((void**)&WvT, g_WvT);
    cudaGetSymbolAddress((void**)&WoT, g_WoT);

    cudaFuncSetAttribute(gemm_qkv,
                         cudaFuncAttributeMaxDynamicSharedMemorySize, GEMM_SMEM);
    cudaFuncSetAttribute(gemm_out,
                         cudaFuncAttributeMaxDynamicSharedMemorySize, GEMM_SMEM);
    cudaFuncSetAttribute(flash_attn_mma,
                         cudaFuncAttributeMaxDynamicSharedMemorySize, FLASH_SMEM);

    // fused prep
    {
        dim3 g(128, 64, 5);
        prep_kernel<<<g, 256>>>(x, Wq, Wk, Wv, Wo, X16, WqT, WkT, WvT, WoT);
    }

    // fused QKV projection (rope + scale fused into epilogue)
    {
        dim3 g(24, Mrows / 128);      // 24 x 32 = 768 CTAs
        gemm_qkv<<<g, 128, GEMM_SMEM>>>(X16, WqT, WkT, WvT,
                                        Q16, K16, V16, fc, fs);
    }

    // attention (fp16 HMMA flash)
    {
        dim3 g(Tn / 128, NH, Bn);     // 16 x 16 x 2
        flash_attn_mma<<<g, 256, FLASH_SMEM>>>(Q16, K16, V16, Y16);
    }

    // output projection
    {
        dim3 go(Cn / 128, Mrows / 128);   // 16 x 32
        gemm_out<<<go, 128, GEMM_SMEM>>>(Y16, WoT, out, Cn, Cn);
    }
}

// round 14
// speedup vs baseline: 1.0175x; 1.0175x over previous
#include <cuda_runtime.h>
#include <cuda_fp16.h>
#include <cstdint>
#include <math.h>

// Problem constants
#define Bn   2
#define Tn   2048
#define Cn   2048
#define NH   16
#define NKV  4
#define HD   128
#define REP  (NH / NKV)          // 4
#define Mrows (Bn * Tn)          // 4096
#define KVC  (NKV * HD)          // 512

// ===========================================================================
// Scratch (device globals; no runtime allocation allowed)
// ===========================================================================
__device__ __half g_X16[(size_t)Mrows * Cn];
__device__ __half g_Q16[(size_t)Mrows * Cn];
__device__ __half g_K16[(size_t)Mrows * KVC];
__device__ __half g_V16[(size_t)Mrows * KVC];
__device__ __half g_Y16[(size_t)Mrows * Cn];

// transposed weights [N][K] (K-major) fp16
__device__ __half g_WqT[(size_t)Cn * Cn];
__device__ __half g_WkT[(size_t)KVC * Cn];
__device__ __half g_WvT[(size_t)KVC * Cn];
__device__ __half g_WoT[(size_t)Cn * Cn];

// ===========================================================================
// PTX helpers
// ===========================================================================
__device__ __forceinline__ uint32_t smem_u32(const void* p) {
    uint32_t a;
    asm("{ .reg .u64 t; cvta.to.shared.u64 t, %1; cvt.u32.u64 %0, t; }"
        : "=r"(a) : "l"(p));
    return a;
}
__device__ __forceinline__ void cp_async16(uint32_t dst, const void* src) {
    asm volatile("cp.async.cg.shared.global [%0], [%1], 16;"
                 :: "r"(dst), "l"(src) : "memory");
}
__device__ __forceinline__ void cp_commit() {
    asm volatile("cp.async.commit_group;" ::: "memory");
}
template <int N> __device__ __forceinline__ void cp_wait_group() {
    asm volatile("cp.async.wait_group %0;" :: "n"(N) : "memory");
}
__device__ __forceinline__ void ldsm_x4(uint32_t* r, uint32_t addr) {
    asm volatile("ldmatrix.sync.aligned.m8n8.x4.shared.b16 {%0,%1,%2,%3}, [%4];"
                 : "=r"(r[0]), "=r"(r[1]), "=r"(r[2]), "=r"(r[3]) : "r"(addr));
}
__device__ __forceinline__ void ldsm_x4_t(uint32_t* r, uint32_t addr) {
    asm volatile("ldmatrix.sync.aligned.m8n8.x4.trans.shared.b16 {%0,%1,%2,%3}, [%4];"
                 : "=r"(r[0]), "=r"(r[1]), "=r"(r[2]), "=r"(r[3]) : "r"(addr));
}
__device__ __forceinline__ void mma16816(float* c, const uint32_t* a, const uint32_t* b) {
    asm volatile(
        "mma.sync.aligned.m16n8k16.row.col.f32.f16.f16.f32 "
        "{%0,%1,%2,%3}, {%4,%5,%6,%7}, {%8,%9}, {%0,%1,%2,%3};"
        : "+f"(c[0]), "+f"(c[1]), "+f"(c[2]), "+f"(c[3])
        : "r"(a[0]), "r"(a[1]), "r"(a[2]), "r"(a[3]), "r"(b[0]), "r"(b[1]));
}
__device__ __forceinline__ uint32_t pack_h2(float a, float b) {
    __half2 t = __floats2half2_rn(a, b);
    return *(uint32_t*)&t;
}

// ===========================================================================
// Fused prep: z = 0..3 -> transpose+convert Wq/Wk/Wv/Wo;  z = 4 -> convert X
// grid (128, 64, 5)
// ===========================================================================
__global__ __launch_bounds__(256)
void prep_kernel(const float* __restrict__ x,
                 const float* __restrict__ Wq, const float* __restrict__ Wk,
                 const float* __restrict__ Wv, const float* __restrict__ Wo,
                 __half* __restrict__ X16,
                 __half* __restrict__ WqT, __half* __restrict__ WkT,
                 __half* __restrict__ WvT, __half* __restrict__ WoT)
{
    const int z = blockIdx.z;
    if (z == 4) {
        int i = (blockIdx.y * gridDim.x + blockIdx.x) * 256 + threadIdx.x;
        int total4 = (Mrows * Cn) / 4;   // 2M
        if (i < total4) {
            float4 v = ((const float4*)x)[i];
            ((__half2*)X16)[2 * i]     = __floats2half2_rn(v.x, v.y);
            ((__half2*)X16)[2 * i + 1] = __floats2half2_rn(v.z, v.w);
        }
        return;
    }
    const float* W;
    __half* T;
    int N;
    if (z == 0)      { W = Wq; T = WqT; N = Cn; }
    else if (z == 1) { W = Wk; T = WkT; N = KVC; }
    else if (z == 2) { W = Wv; T = WvT; N = KVC; }
    else             { W = Wo; T = WoT; N = Cn; }
    const int K = Cn;
    int n0 = blockIdx.x * 32, k0 = blockIdx.y * 32;
    if (n0 >= N) return;

    __shared__ float tile[32][33];
    int tx = threadIdx.x & 31, ty = threadIdx.x >> 5;
#pragma unroll
    for (int i = 0; i < 32; i += 8)
        tile[ty + i][tx] = W[(size_t)(k0 + ty + i) * N + n0 + tx];
    __syncthreads();
#pragma unroll
    for (int i = 0; i < 32; i += 8)
        T[(size_t)(n0 + ty + i) * K + k0 + tx] = __float2half(tile[tx][ty + i]);
}

// ===========================================================================
// fp16 HMMA GEMM: C[M,N] = A @ B^T (fp32 acc)
// 128x128 CTA tile, BK=64, 128 threads / 4 warps (2x2), 64x64 warp tiles,
// 2-stage cp.async pipeline; prefetch spread across kk steps; hoisted ptrs.
// MODE 0: fp32 out. MODE 1: fp16 out. MODE 2: rope + fp16 out.
// MODE 3: rope + attn-scale(incl. log2e) + fp16 out (for Q).
// ===========================================================================
#define TBK 64
#define RS  72                            // 64 + 8 pad (halves)
#define MAT_BYTES (128 * RS * 2)          // 18432
#define STG_BYTES (2 * MAT_BYTES)         // 36864
#define GEMM_SMEM (2 * STG_BYTES)         // 73728

// 1/sqrt(128) * log2(e): softmax done in exp2 domain
#define QSCALE 0.1275174103207546f

template <int MODE>
__device__ __forceinline__ void gemm_core(
    const __half* __restrict__ A, const __half* __restrict__ B,
    float* __restrict__ Cf, __half* __restrict__ Ch,
    int ldc, int K,
    const float* __restrict__ fcos, const float* __restrict__ fsin, int rowg0)
{
    extern __shared__ char smem[];
    const uint32_t sb = smem_u32(smem);
    const int tid = threadIdx.x;
    const int lane = tid & 31;
    const int wid = tid >> 5;        // 0..3
    const int wm = wid & 1;
    const int wn = wid >> 1;

    float acc[4][8][4];
#pragma unroll
    for (int i = 0; i < 4; i++)
#pragma unroll
        for (int j = 0; j < 8; j++)
#pragma unroll
            for (int q = 0; q < 4; q++) acc[i][j][q] = 0.f;

    const int a_row_in = (lane & 15);
    const int a_koff   = (lane >> 4) * 8;
    const int b_row_in = (lane & 7) + ((lane >> 4) * 8);
    const int b_koff   = ((lane >> 3) & 1) * 8;

    // hoisted per-thread cp.async addressing
    const int ld_r0  = tid >> 3;
    const int ld_seg = tid & 7;
    const __half* Aptr[8];
    const __half* Bptr[8];
    uint32_t soff[8];
#pragma unroll
    for (int j = 0; j < 8; j++) {
        int r = ld_r0 + j * 16;
        soff[j] = (uint32_t)(r * (RS * 2) + ld_seg * 16);
        Aptr[j] = A + (size_t)r * K + ld_seg * 8;
        Bptr[j] = B + (size_t)r * K + ld_seg * 8;
    }

    const int NC = K / TBK;
    {
        uint32_t st = sb;
#pragma unroll
        for (int j = 0; j < 8; j++) {
            cp_async16(st + soff[j],             Aptr[j]);
            cp_async16(st + MAT_BYTES + soff[j], Bptr[j]);
            Aptr[j] += TBK; Bptr[j] += TBK;
        }
        cp_commit();
    }

    for (int c = 0; c < NC; c++) {
        cp_wait_group<0>();
        __syncthreads();

        const uint32_t st = sb + (c & 1) * STG_BYTES;
        const uint32_t stn = sb + ((c + 1) & 1) * STG_BYTES;
        const bool pf = (c + 1 < NC);

#pragma unroll
        for (int kk = 0; kk < 4; kk++) {
            const int k0 = kk * 16;
            uint32_t af[4][4];
#pragma unroll
            for (int mt = 0; mt < 4; mt++) {
                int row = wm * 64 + mt * 16 + a_row_in;
                ldsm_x4(af[mt], st + (uint32_t)(row * (RS * 2) + (k0 + a_koff) * 2));
            }
            uint32_t bf[4][4];
#pragma unroll
            for (int nt = 0; nt < 4; nt++) {
                int rowb = wn * 64 + nt * 16 + b_row_in;
                ldsm_x4(bf[nt], st + MAT_BYTES
                        + (uint32_t)(rowb * (RS * 2) + (k0 + b_koff) * 2));
            }
            if (pf) {
#pragma unroll
                for (int j = 2 * kk; j < 2 * kk + 2; j++) {
                    cp_async16(stn + soff[j],             Aptr[j]);
                    cp_async16(stn + MAT_BYTES + soff[j], Bptr[j]);
                    Aptr[j] += TBK; Bptr[j] += TBK;
                }
            }
#pragma unroll
            for (int mt = 0; mt < 4; mt++)
#pragma unroll
                for (int nt = 0; nt < 4; nt++) {
                    mma16816(acc[mt][2 * nt],     af[mt], bf[nt]);
                    mma16816(acc[mt][2 * nt + 1], af[mt], bf[nt] + 2);
                }
        }
        if (pf) cp_commit();
    }

#pragma unroll
    for (int mt = 0; mt < 4; mt++) {
#pragma unroll
        for (int nt = 0; nt < 8; nt++) {
            int row = wm * 64 + mt * 16 + (lane >> 2);
            int col = wn * 64 + nt * 8 + (lane & 3) * 2;
            float v0 = acc[mt][nt][0], v1 = acc[mt][nt][1];
            float v2 = acc[mt][nt][2], v3 = acc[mt][nt][3];
            if (MODE == 0) {
                *(float2*)(Cf + (size_t)row * ldc + col) = make_float2(v0, v1);
                *(float2*)(Cf + (size_t)(row + 8) * ldc + col) = make_float2(v2, v3);
            } else {
                if (MODE >= 2) {
                    int i = (col & 127) >> 1;
                    int t1 = (rowg0 + row) & (Tn - 1);
                    int t2 = (rowg0 + row + 8) & (Tn - 1);
                    float c1 = fcos[t1 * 64 + i], s1 = fsin[t1 * 64 + i];
                    float c2 = fcos[t2 * 64 + i], s2 = fsin[t2 * 64 + i];
                    float re = v0, im = v1;
                    v0 = re * c1 - im * s1; v1 = re * s1 + im * c1;
                    re = v2; im = v3;
                    v2 = re * c2 - im * s2; v3 = re * s2 + im * c2;
                    if (MODE == 3) {
                        v0 *= QSCALE; v1 *= QSCALE; v2 *= QSCALE; v3 *= QSCALE;
                    }
                }
                *(__half2*)(Ch + (size_t)row * ldc + col) = __floats2half2_rn(v0, v1);
                *(__half2*)(Ch + (size_t)(row + 8) * ldc + col) = __floats2half2_rn(v2, v3);
            }
        }
    }
}

// Fused QKV projection: grid (24, 32). Col tiles 0-15 -> Q (rope+scale),
// 16-19 -> K (rope), 20-23 -> V
__global__ __launch_bounds__(128)
void gemm_qkv(const __half* __restrict__ X16,
              const __half* __restrict__ WqT, const __half* __restrict__ WkT,
              const __half* __restrict__ WvT,
              __half* __restrict__ Q, __half* __restrict__ Ko, __half* __restrict__ Vo,
              const float* __restrict__ fcos, const float* __restrict__ fsin)
{
    const int ct = blockIdx.x;
    const int row0 = blockIdx.y * 128;
    const __half* Xp = X16 + (size_t)row0 * Cn;
    if (ct < 16) {
        int c0 = ct * 128;
        gemm_core<3>(Xp, WqT + (size_t)c0 * Cn, nullptr,
                     Q + (size_t)row0 * Cn + c0, Cn, Cn, fcos, fsin, row0);
    } else if (ct < 20) {
        int c0 = (ct - 16) * 128;
        gemm_core<2>(Xp, WkT + (size_t)c0 * Cn, nullptr,
                     Ko + (size_t)row0 * KVC + c0, KVC, Cn, fcos, fsin, row0);
    } else {
        int c0 = (ct - 20) * 128;
        gemm_core<1>(Xp, WvT + (size_t)c0 * Cn, nullptr,
                     Vo + (size_t)row0 * KVC + c0, KVC, Cn, nullptr, nullptr, row0);
    }
}

// Output projection GEMM (fp32 out)
__global__ __launch_bounds__(128)
void gemm_out(const __half* __restrict__ A, const __half* __restrict__ B,
              float* __restrict__ C, int N, int K)
{
    const int row0 = blockIdx.y * 128;
    const int col0 = blockIdx.x * 128;
    gemm_core<0>(A + (size_t)row0 * K, B + (size_t)col0 * K,
                 C + (size_t)row0 * N + col0, nullptr,
                 N, K, nullptr, nullptr, 0);
}

// ===========================================================================
// Flash attention on fp16 HMMA (causal, GQA)
// Q pre-scaled by (1/sqrt(d))*log2e -> softmax in exp2 domain.
// Single barrier per tile: wait -> barrier -> prefetch -> compute.
// ===========================================================================
#define FST 136
#define FROWB (FST * 2)              // 272 bytes per row
#define QTILE_B (128 * FROWB)        // 34816
#define KTILE_B (64 * FROWB)         // 17408
#define KVSTG_B (2 * KTILE_B)        // 34816 per stage (K+V)
#define FLASH_SMEM (QTILE_B + 2 * KVSTG_B)   // 104448

__global__ __launch_bounds__(256)
void flash_attn_mma(const __half* __restrict__ Qg, const __half* __restrict__ Kg,
                    const __half* __restrict__ Vg, __half* __restrict__ Yg)
{
    extern __shared__ char smc[];
    const uint32_t sb  = smem_u32(smc);
    const uint32_t sQ  = sb;
    const uint32_t sKV0 = sb + QTILE_B;

    const int tid = threadIdx.x;
    const int lane = tid & 31;
    const int w = tid >> 5;
    const int bq = gridDim.x - 1 - blockIdx.x;       // heavy blocks first
    const int h = blockIdx.y, b = blockIdx.z;
    const int q0 = bq * 128;
    const int kvh = h / REP;

    const __half* Qp = Qg + ((size_t)b * Tn + q0) * Cn + h * HD;

    // hoisted per-thread K/V load pointers
    const int f_r0  = tid >> 4;
    const int f_seg = tid & 15;
    const __half* Kcur[4];
    const __half* Vcur[4];
    uint32_t foff[4];
    {
        const __half* Kb = Kg + (size_t)b * Tn * KVC + kvh * HD + f_seg * 8;
        const __half* Vb = Vg + (size_t)b * Tn * KVC + kvh * HD + f_seg * 8;
#pragma unroll
        for (int i = 0; i < 4; i++) {
            int r = f_r0 + i * 16;
            foff[i] = (uint32_t)(r * FROWB + f_seg * 16);
            Kcur[i] = Kb + (size_t)r * KVC;
            Vcur[i] = Vb + (size_t)r * KVC;
        }
    }

    // Q tile loads + KV tile 0 (one commit group)
#pragma unroll
    for (int i = 0; i < 8; i++) {
        int idx = tid + i * 256;
        int r = idx >> 4, seg = idx & 15;
        uint32_t off = (uint32_t)(r * FROWB + seg * 16);
        cp_async16(sQ + off, Qp + (size_t)r * Cn + seg * 8);
    }
#pragma unroll
    for (int i = 0; i < 4; i++) {
        cp_async16(sKV0 + foff[i],           Kcur[i]);
        cp_async16(sKV0 + KTILE_B + foff[i], Vcur[i]);
        Kcur[i] += 64 * KVC; Vcur[i] += 64 * KVC;
    }
    cp_commit();

    const int arow = lane & 15;
    const int akoff = (lane >> 4) * 8;
    const int brow = (lane & 7) + ((lane >> 4) * 8);
    const int bkoff = ((lane >> 3) & 1) * 8;
    const int vrow = lane & 15;
    const int vnoff = (lane >> 4) * 8;

    float Oa[16][4];
#pragma unroll
    for (int i = 0; i < 16; i++)
#pragma unroll
        for (int q = 0; q < 4; q++) Oa[i][q] = 0.f;

    float m1 = -1e30f, m2 = -1e30f, l1 = 0.f, l2 = 0.f;
    const int rg1 = q0 + w * 16 + (lane >> 2);
    const int rg2 = rg1 + 8;

    const int nkb = 2 * bq + 2;
    for (int j = 0; j < nkb; j++) {
        const int k0g = j * 64;
        const uint32_t skv = sKV0 + (j & 1) * KVSTG_B;

        // wait for tile j's data, barrier, then issue prefetch for j+1
        cp_wait_group<0>();
        __syncthreads();
        if (j + 1 < nkb) {
            const uint32_t skn = sKV0 + ((j + 1) & 1) * KVSTG_B;
#pragma unroll
            for (int i = 0; i < 4; i++) {
                cp_async16(skn + foff[i],           Kcur[i]);
                cp_async16(skn + KTILE_B + foff[i], Vcur[i]);
                Kcur[i] += 64 * KVC; Vcur[i] += 64 * KVC;
            }
            cp_commit();
        }

        const uint32_t sK = skv;
        const uint32_t sV = skv + KTILE_B;

        float S[8][4];
#pragma unroll
        for (int t = 0; t < 8; t++)
#pragma unroll
            for (int q = 0; q < 4; q++) S[t][q] = 0.f;

#pragma unroll
        for (int kc = 0; kc < 8; kc++) {
            uint32_t af[4];
            ldsm_x4(af, sQ + (uint32_t)((w * 16 + arow) * FROWB + (kc * 16 + akoff) * 2));
#pragma unroll
            for (int np = 0; np < 4; np++) {
                uint32_t bf[4];
                ldsm_x4(bf, sK + (uint32_t)((np * 16 + brow) * FROWB + (kc * 16 + bkoff) * 2));
                mma16816(S[2 * np],     af, bf);
                mma16816(S[2 * np + 1], af, bf + 2);
            }
        }

        // mask + online softmax (exp2 domain; Q carries log2e)
        const bool diag = (k0g + 63 > q0 + w * 16);
        float mx1 = -1e30f, mx2 = -1e30f;
#pragma unroll
        for (int t = 0; t < 8; t++) {
            int cg = k0g + t * 8 + (lane & 3) * 2;
#pragma unroll
            for (int e = 0; e < 2; e++) {
                float s0 = S[t][e];
                float s1 = S[t][2 + e];
                if (diag) {
                    if (cg + e > rg1) s0 = -1e30f;
                    if (cg + e > rg2) s1 = -1e30f;
                }
                S[t][e] = s0;
                S[t][2 + e] = s1;
                mx1 = fmaxf(mx1, s0);
                mx2 = fmaxf(mx2, s1);
            }
        }
        mx1 = fmaxf(mx1, __shfl_xor_sync(0xffffffff, mx1, 1));
        mx1 = fmaxf(mx1, __shfl_xor_sync(0xffffffff, mx1, 2));
        mx2 = fmaxf(mx2, __shfl_xor_sync(0xffffffff, mx2, 1));
        mx2 = fmaxf(mx2, __shfl_xor_sync(0xffffffff, mx2, 2));

        float mn1 = fmaxf(m1, mx1), mn2 = fmaxf(m2, mx2);
        float f1 = exp2f(m1 - mn1), f2 = exp2f(m2 - mn2);
        float rs1 = 0.f, rs2 = 0.f;
#pragma unroll
        for (int t = 0; t < 8; t++) {
#pragma unroll
            for (int e = 0; e < 2; e++) {
                float p0 = exp2f(S[t][e] - mn1);
                float p1 = exp2f(S[t][2 + e] - mn2);
                S[t][e] = p0;
                S[t][2 + e] = p1;
                rs1 += p0;
                rs2 += p1;
            }
        }
        rs1 += __shfl_xor_sync(0xffffffff, rs1, 1);
        rs1 += __shfl_xor_sync(0xffffffff, rs1, 2);
        rs2 += __shfl_xor_sync(0xffffffff, rs2, 1);
        rs2 += __shfl_xor_sync(0xffffffff, rs2, 2);
        l1 = l1 * f1 + rs1;
        l2 = l2 * f2 + rs2;
        m1 = mn1; m2 = mn2;
#pragma unroll
        for (int t = 0; t < 16; t++) {
            Oa[t][0] *= f1; Oa[t][1] *= f1;
            Oa[t][2] *= f2; Oa[t][3] *= f2;
        }

#pragma unroll
        for (int kc = 0; kc < 4; kc++) {
            uint32_t pf[4];
            pf[0] = pack_h2(S[2 * kc][0],     S[2 * kc][1]);
            pf[1] = pack_h2(S[2 * kc][2],     S[2 * kc][3]);
            pf[2] = pack_h2(S[2 * kc + 1][0], S[2 * kc + 1][1]);
            pf[3] = pack_h2(S[2 * kc + 1][2], S[2 * kc + 1][3]);
#pragma unroll
            for (int np = 0; np < 8; np++) {
                uint32_t vf[4];
                ldsm_x4_t(vf, sV + (uint32_t)((kc * 16 + vrow) * FROWB
                                              + (np * 16 + vnoff) * 2));
                mma16816(Oa[2 * np],     pf, vf);
                mma16816(Oa[2 * np + 1], pf, vf + 2);
            }
        }
    }

    const float il1 = 1.f / l1, il2 = 1.f / l2;
    const size_t base1 = ((size_t)b * Tn + q0 + w * 16 + (lane >> 2)) * Cn + h * HD;
    const size_t base2 = base1 + 8 * (size_t)Cn;
#pragma unroll
    for (int nt = 0; nt < 16; nt++) {
        int col = nt * 8 + (lane & 3) * 2;
        *(__half2*)(Yg + base1 + col) =
            __floats2half2_rn(Oa[nt][0] * il1, Oa[nt][1] * il1);
        *(__half2*)(Yg + base2 + col) =
            __floats2half2_rn(Oa[nt][2] * il2, Oa[nt][3] * il2);
    }
}

// ===========================================================================
// launch
// ===========================================================================
extern "C" void kernel_launch(void* const* d_in, const int* in_sizes, int n_in,
                              void* d_out, int out_size)
{
    const float* x   = (const float*)d_in[0];
    const float* Wq  = (const float*)d_in[1];
    const float* Wk  = (const float*)d_in[2];
    const float* Wv  = (const float*)d_in[3];
    const float* Wo  = (const float*)d_in[4];
    const float* fc  = (const float*)d_in[5];
    const float* fs  = (const float*)d_in[6];
    float* out = (float*)d_out;

    __half *X16, *Q16, *K16, *V16, *Y16, *WqT, *WkT, *WvT, *WoT;
    cudaGetSymbolAddress((void**)&X16, g_X16);
    cudaGetSymbolAddress((void**)&Q16, g_Q16);
    cudaGetSymbolAddress((void**)&K16, g_K16);
    cudaGetSymbolAddress((void**)&V16, g_V16);
    cudaGetSymbolAddress((void**)&Y16, g_Y16);
    cudaGetSymbolAddress((void**)&WqT, g_WqT);
    cudaGetSymbolAddress((void**)&WkT, g_WkT);
    cudaGetSymbolAddress((void**)&WvT, g_WvT);
    cudaGetSymbolAddress((void**)&WoT, g_WoT);

    cudaFuncSetAttribute(gemm_qkv,
                         cudaFuncAttributeMaxDynamicSharedMemorySize, GEMM_SMEM);
    cudaFuncSetAttribute(gemm_out,
                         cudaFuncAttributeMaxDynamicSharedMemorySize, GEMM_SMEM);
    cudaFuncSetAttribute(flash_attn_mma,
                         cudaFuncAttributeMaxDynamicSharedMemorySize, FLASH_SMEM);

    // fused prep
    {
        dim3 g(128, 64, 5);
        prep_kernel<<<g, 256>>>(x, Wq, Wk, Wv, Wo, X16, WqT, WkT, WvT, WoT);
    }

    // fused QKV projection (rope + exp2-scale fused into epilogue)
    {
        dim3 g(24, Mrows / 128);      // 24 x 32 = 768 CTAs
        gemm_qkv<<<g, 128, GEMM_SMEM>>>(X16, WqT, WkT, WvT,
                                        Q16, K16, V16, fc, fs);
    }

    // attention (fp16 HMMA flash)
    {
        dim3 g(Tn / 128, NH, Bn);     // 16 x 16 x 2
        flash_attn_mma<<<g, 256, FLASH_SMEM>>>(Q16, K16, V16, Y16);
    }

    // output projection
    {
        dim3 go(Cn / 128, Mrows / 128);   // 16 x 32
        gemm_out<<<go, 128, GEMM_SMEM>>>(Y16, WoT, out, Cn, Cn);
    }
}

// round 15
// speedup vs baseline: 1.0420x; 1.0241x over previous
#include <cuda_runtime.h>
#include <cuda_fp16.h>
#include <cstdint>
#include <math.h>

// Problem constants
#define Bn   2
#define Tn   2048
#define Cn   2048
#define NH   16
#define NKV  4
#define HD   128
#define REP  (NH / NKV)          // 4
#define Mrows (Bn * Tn)          // 4096
#define KVC  (NKV * HD)          // 512

// ===========================================================================
// Scratch (device globals; no runtime allocation allowed)
// ===========================================================================
__device__ __half g_X16[(size_t)Mrows * Cn];
__device__ __half g_Q16[(size_t)Mrows * Cn];
__device__ __half g_K16[(size_t)Mrows * KVC];
__device__ __half g_V16[(size_t)Mrows * KVC];
__device__ __half g_Y16[(size_t)Mrows * Cn];

// transposed weights [N][K] (K-major) fp16
__device__ __half g_WqT[(size_t)Cn * Cn];
__device__ __half g_WkT[(size_t)KVC * Cn];
__device__ __half g_WvT[(size_t)KVC * Cn];
__device__ __half g_WoT[(size_t)Cn * Cn];

// ===========================================================================
// PTX helpers
// ===========================================================================
__device__ __forceinline__ uint32_t smem_u32(const void* p) {
    uint32_t a;
    asm("{ .reg .u64 t; cvta.to.shared.u64 t, %1; cvt.u32.u64 %0, t; }"
        : "=r"(a) : "l"(p));
    return a;
}
__device__ __forceinline__ void cp_async16(uint32_t dst, const void* src) {
    asm volatile("cp.async.cg.shared.global [%0], [%1], 16;"
                 :: "r"(dst), "l"(src) : "memory");
}
__device__ __forceinline__ void cp_commit() {
    asm volatile("cp.async.commit_group;" ::: "memory");
}
template <int N> __device__ __forceinline__ void cp_wait_group() {
    asm volatile("cp.async.wait_group %0;" :: "n"(N) : "memory");
}
__device__ __forceinline__ void ldsm_x4(uint32_t* r, uint32_t addr) {
    asm volatile("ldmatrix.sync.aligned.m8n8.x4.shared.b16 {%0,%1,%2,%3}, [%4];"
                 : "=r"(r[0]), "=r"(r[1]), "=r"(r[2]), "=r"(r[3]) : "r"(addr));
}
__device__ __forceinline__ void ldsm_x4_t(uint32_t* r, uint32_t addr) {
    asm volatile("ldmatrix.sync.aligned.m8n8.x4.trans.shared.b16 {%0,%1,%2,%3}, [%4];"
                 : "=r"(r[0]), "=r"(r[1]), "=r"(r[2]), "=r"(r[3]) : "r"(addr));
}
// fp32 accumulate
__device__ __forceinline__ void mma16816(float* c, const uint32_t* a, const uint32_t* b) {
    asm volatile(
        "mma.sync.aligned.m16n8k16.row.col.f32.f16.f16.f32 "
        "{%0,%1,%2,%3}, {%4,%5,%6,%7}, {%8,%9}, {%0,%1,%2,%3};"
        : "+f"(c[0]), "+f"(c[1]), "+f"(c[2]), "+f"(c[3])
        : "r"(a[0]), "r"(a[1]), "r"(a[2]), "r"(a[3]), "r"(b[0]), "r"(b[1]));
}
// fp16 accumulate (2x issue rate) — used for flash S = Q K^T only
__device__ __forceinline__ void mma16816_h(uint32_t* c, const uint32_t* a, const uint32_t* b) {
    asm volatile(
        "mma.sync.aligned.m16n8k16.row.col.f16.f16.f16.f16 "
        "{%0,%1}, {%2,%3,%4,%5}, {%6,%7}, {%0,%1};"
        : "+r"(c[0]), "+r"(c[1])
        : "r"(a[0]), "r"(a[1]), "r"(a[2]), "r"(a[3]), "r"(b[0]), "r"(b[1]));
}
__device__ __forceinline__ uint32_t pack_h2(float a, float b) {
    __half2 t = __floats2half2_rn(a, b);
    return *(uint32_t*)&t;
}

// ===========================================================================
// Fused prep: z = 0..3 -> transpose+convert Wq/Wk/Wv/Wo;  z = 4 -> convert X
// grid (128, 64, 5)
// ===========================================================================
__global__ __launch_bounds__(256)
void prep_kernel(const float* __restrict__ x,
                 const float* __restrict__ Wq, const float* __restrict__ Wk,
                 const float* __restrict__ Wv, const float* __restrict__ Wo,
                 __half* __restrict__ X16,
                 __half* __restrict__ WqT, __half* __restrict__ WkT,
                 __half* __restrict__ WvT, __half* __restrict__ WoT)
{
    const int z = blockIdx.z;
    if (z == 4) {
        int i = (blockIdx.y * gridDim.x + blockIdx.x) * 256 + threadIdx.x;
        int total4 = (Mrows * Cn) / 4;   // 2M
        if (i < total4) {
            float4 v = ((const float4*)x)[i];
            ((__half2*)X16)[2 * i]     = __floats2half2_rn(v.x, v.y);
            ((__half2*)X16)[2 * i + 1] = __floats2half2_rn(v.z, v.w);
        }
        return;
    }
    const float* W;
    __half* T;
    int N;
    if (z == 0)      { W = Wq; T = WqT; N = Cn; }
    else if (z == 1) { W = Wk; T = WkT; N = KVC; }
    else if (z == 2) { W = Wv; T = WvT; N = KVC; }
    else             { W = Wo; T = WoT; N = Cn; }
    const int K = Cn;
    int n0 = blockIdx.x * 32, k0 = blockIdx.y * 32;
    if (n0 >= N) return;

    __shared__ float tile[32][33];
    int tx = threadIdx.x & 31, ty = threadIdx.x >> 5;
#pragma unroll
    for (int i = 0; i < 32; i += 8)
        tile[ty + i][tx] = W[(size_t)(k0 + ty + i) * N + n0 + tx];
    __syncthreads();
#pragma unroll
    for (int i = 0; i < 32; i += 8)
        T[(size_t)(n0 + ty + i) * K + k0 + tx] = __float2half(tile[tx][ty + i]);
}

// ===========================================================================
// fp16 HMMA GEMM: C[M,N] = A @ B^T (fp32 acc)
// 128x128 CTA tile, BK=64, 128 threads / 4 warps (2x2), 64x64 warp tiles,
// 2-stage cp.async pipeline; prefetch spread across kk steps; hoisted ptrs.
// MODE 0: fp32 out. MODE 1: fp16 out. MODE 2: rope + fp16 out.
// MODE 3: rope + attn-scale(incl. log2e) + fp16 out (for Q).
// ===========================================================================
#define TBK 64
#define RS  72                            // 64 + 8 pad (halves)
#define MAT_BYTES (128 * RS * 2)          // 18432
#define STG_BYTES (2 * MAT_BYTES)         // 36864
#define GEMM_SMEM (2 * STG_BYTES)         // 73728

// 1/sqrt(128) * log2(e): softmax done in exp2 domain
#define QSCALE 0.1275174103207546f

template <int MODE>
__device__ __forceinline__ void gemm_core(
    const __half* __restrict__ A, const __half* __restrict__ B,
    float* __restrict__ Cf, __half* __restrict__ Ch,
    int ldc, int K,
    const float* __restrict__ fcos, const float* __restrict__ fsin, int rowg0)
{
    extern __shared__ char smem[];
    const uint32_t sb = smem_u32(smem);
    const int tid = threadIdx.x;
    const int lane = tid & 31;
    const int wid = tid >> 5;        // 0..3
    const int wm = wid & 1;
    const int wn = wid >> 1;

    float acc[4][8][4];
#pragma unroll
    for (int i = 0; i < 4; i++)
#pragma unroll
        for (int j = 0; j < 8; j++)
#pragma unroll
            for (int q = 0; q < 4; q++) acc[i][j][q] = 0.f;

    const int a_row_in = (lane & 15);
    const int a_koff   = (lane >> 4) * 8;
    const int b_row_in = (lane & 7) + ((lane >> 4) * 8);
    const int b_koff   = ((lane >> 3) & 1) * 8;

    // hoisted per-thread cp.async addressing
    const int ld_r0  = tid >> 3;
    const int ld_seg = tid & 7;
    const __half* Aptr[8];
    const __half* Bptr[8];
    uint32_t soff[8];
#pragma unroll
    for (int j = 0; j < 8; j++) {
        int r = ld_r0 + j * 16;
        soff[j] = (uint32_t)(r * (RS * 2) + ld_seg * 16);
        Aptr[j] = A + (size_t)r * K + ld_seg * 8;
        Bptr[j] = B + (size_t)r * K + ld_seg * 8;
    }

    const int NC = K / TBK;
    {
        uint32_t st = sb;
#pragma unroll
        for (int j = 0; j < 8; j++) {
            cp_async16(st + soff[j],             Aptr[j]);
            cp_async16(st + MAT_BYTES + soff[j], Bptr[j]);
            Aptr[j] += TBK; Bptr[j] += TBK;
        }
        cp_commit();
    }

    for (int c = 0; c < NC; c++) {
        cp_wait_group<0>();
        __syncthreads();

        const uint32_t st = sb + (c & 1) * STG_BYTES;
        const uint32_t stn = sb + ((c + 1) & 1) * STG_BYTES;
        const bool pf = (c + 1 < NC);

#pragma unroll
        for (int kk = 0; kk < 4; kk++) {
            const int k0 = kk * 16;
            uint32_t af[4][4];
#pragma unroll
            for (int mt = 0; mt < 4; mt++) {
                int row = wm * 64 + mt * 16 + a_row_in;
                ldsm_x4(af[mt], st + (uint32_t)(row * (RS * 2) + (k0 + a_koff) * 2));
            }
            uint32_t bf[4][4];
#pragma unroll
            for (int nt = 0; nt < 4; nt++) {
                int rowb = wn * 64 + nt * 16 + b_row_in;
                ldsm_x4(bf[nt], st + MAT_BYTES
                        + (uint32_t)(rowb * (RS * 2) + (k0 + b_koff) * 2));
            }
            if (pf) {
#pragma unroll
                for (int j = 2 * kk; j < 2 * kk + 2; j++) {
                    cp_async16(stn + soff[j],             Aptr[j]);
                    cp_async16(stn + MAT_BYTES + soff[j], Bptr[j]);
                    Aptr[j] += TBK; Bptr[j] += TBK;
                }
            }
#pragma unroll
            for (int mt = 0; mt < 4; mt++)
#pragma unroll
                for (int nt = 0; nt < 4; nt++) {
                    mma16816(acc[mt][2 * nt],     af[mt], bf[nt]);
                    mma16816(acc[mt][2 * nt + 1], af[mt], bf[nt] + 2);
                }
        }
        if (pf) cp_commit();
    }

#pragma unroll
    for (int mt = 0; mt < 4; mt++) {
#pragma unroll
        for (int nt = 0; nt < 8; nt++) {
            int row = wm * 64 + mt * 16 + (lane >> 2);
            int col = wn * 64 + nt * 8 + (lane & 3) * 2;
            float v0 = acc[mt][nt][0], v1 = acc[mt][nt][1];
            float v2 = acc[mt][nt][2], v3 = acc[mt][nt][3];
            if (MODE == 0) {
                *(float2*)(Cf + (size_t)row * ldc + col) = make_float2(v0, v1);
                *(float2*)(Cf + (size_t)(row + 8) * ldc + col) = make_float2(v2, v3);
            } else {
                if (MODE >= 2) {
                    int i = (col & 127) >> 1;
                    int t1 = (rowg0 + row) & (Tn - 1);
                    int t2 = (rowg0 + row + 8) & (Tn - 1);
                    float c1 = fcos[t1 * 64 + i], s1 = fsin[t1 * 64 + i];
                    float c2 = fcos[t2 * 64 + i], s2 = fsin[t2 * 64 + i];
                    float re = v0, im = v1;
                    v0 = re * c1 - im * s1; v1 = re * s1 + im * c1;
                    re = v2; im = v3;
                    v2 = re * c2 - im * s2; v3 = re * s2 + im * c2;
                    if (MODE == 3) {
                        v0 *= QSCALE; v1 *= QSCALE; v2 *= QSCALE; v3 *= QSCALE;
                    }
                }
                *(__half2*)(Ch + (size_t)row * ldc + col) = __floats2half2_rn(v0, v1);
                *(__half2*)(Ch + (size_t)(row + 8) * ldc + col) = __floats2half2_rn(v2, v3);
            }
        }
    }
}

// Fused QKV projection: grid (24, 32). Col tiles 0-15 -> Q (rope+scale),
// 16-19 -> K (rope), 20-23 -> V
__global__ __launch_bounds__(128)
void gemm_qkv(const __half* __restrict__ X16,
              const __half* __restrict__ WqT, const __half* __restrict__ WkT,
              const __half* __restrict__ WvT,
              __half* __restrict__ Q, __half* __restrict__ Ko, __half* __restrict__ Vo,
              const float* __restrict__ fcos, const float* __restrict__ fsin)
{
    const int ct = blockIdx.x;
    const int row0 = blockIdx.y * 128;
    const __half* Xp = X16 + (size_t)row0 * Cn;
    if (ct < 16) {
        int c0 = ct * 128;
        gemm_core<3>(Xp, WqT + (size_t)c0 * Cn, nullptr,
                     Q + (size_t)row0 * Cn + c0, Cn, Cn, fcos, fsin, row0);
    } else if (ct < 20) {
        int c0 = (ct - 16) * 128;
        gemm_core<2>(Xp, WkT + (size_t)c0 * Cn, nullptr,
                     Ko + (size_t)row0 * KVC + c0, KVC, Cn, fcos, fsin, row0);
    } else {
        int c0 = (ct - 20) * 128;
        gemm_core<1>(Xp, WvT + (size_t)c0 * Cn, nullptr,
                     Vo + (size_t)row0 * KVC + c0, KVC, Cn, nullptr, nullptr, row0);
    }
}

// Output projection GEMM (fp32 out)
__global__ __launch_bounds__(128)
void gemm_out(const __half* __restrict__ A, const __half* __restrict__ B,
              float* __restrict__ C, int N, int K)
{
    const int row0 = blockIdx.y * 128;
    const int col0 = blockIdx.x * 128;
    gemm_core<0>(A + (size_t)row0 * K, B + (size_t)col0 * K,
                 C + (size_t)row0 * N + col0, nullptr,
                 N, K, nullptr, nullptr, 0);
}

// ===========================================================================
// Flash attention on fp16 HMMA (causal, GQA)
// Q pre-scaled by (1/sqrt(d))*log2e -> softmax in exp2 domain.
// S = Q K^T uses fp16 accumulate (2x mma rate); P V stays fp32 accumulate.
// ===========================================================================
#define FST 136
#define FROWB (FST * 2)              // 272 bytes per row
#define QTILE_B (128 * FROWB)        // 34816
#define KTILE_B (64 * FROWB)         // 17408
#define KVSTG_B (2 * KTILE_B)        // 34816 per stage (K+V)
#define FLASH_SMEM (QTILE_B + 2 * KVSTG_B)   // 104448

__global__ __launch_bounds__(256)
void flash_attn_mma(const __half* __restrict__ Qg, const __half* __restrict__ Kg,
                    const __half* __restrict__ Vg, __half* __restrict__ Yg)
{
    extern __shared__ char smc[];
    const uint32_t sb  = smem_u32(smc);
    const uint32_t sQ  = sb;
    const uint32_t sKV0 = sb + QTILE_B;

    const int tid = threadIdx.x;
    const int lane = tid & 31;
    const int w = tid >> 5;
    const int bq = gridDim.x - 1 - blockIdx.x;       // heavy blocks first
    const int h = blockIdx.y, b = blockIdx.z;
    const int q0 = bq * 128;
    const int kvh = h / REP;

    const __half* Qp = Qg + ((size_t)b * Tn + q0) * Cn + h * HD;

    // hoisted per-thread K/V load pointers
    const int f_r0  = tid >> 4;
    const int f_seg = tid & 15;
    const __half* Kcur[4];
    const __half* Vcur[4];
    uint32_t foff[4];
    {
        const __half* Kb = Kg + (size_t)b * Tn * KVC + kvh * HD + f_seg * 8;
        const __half* Vb = Vg + (size_t)b * Tn * KVC + kvh * HD + f_seg * 8;
#pragma unroll
        for (int i = 0; i < 4; i++) {
            int r = f_r0 + i * 16;
            foff[i] = (uint32_t)(r * FROWB + f_seg * 16);
            Kcur[i] = Kb + (size_t)r * KVC;
            Vcur[i] = Vb + (size_t)r * KVC;
        }
    }

    // Q tile loads + KV tile 0 (one commit group)
#pragma unroll
    for (int i = 0; i < 8; i++) {
        int idx = tid + i * 256;
        int r = idx >> 4, seg = idx & 15;
        uint32_t off = (uint32_t)(r * FROWB + seg * 16);
        cp_async16(sQ + off, Qp + (size_t)r * Cn + seg * 8);
    }
#pragma unroll
    for (int i = 0; i < 4; i++) {
        cp_async16(sKV0 + foff[i],           Kcur[i]);
        cp_async16(sKV0 + KTILE_B + foff[i], Vcur[i]);
        Kcur[i] += 64 * KVC; Vcur[i] += 64 * KVC;
    }
    cp_commit();

    const int arow = lane & 15;
    const int akoff = (lane >> 4) * 8;
    const int brow = (lane & 7) + ((lane >> 4) * 8);
    const int bkoff = ((lane >> 3) & 1) * 8;
    const int vrow = lane & 15;
    const int vnoff = (lane >> 4) * 8;

    float Oa[16][4];
#pragma unroll
    for (int i = 0; i < 16; i++)
#pragma unroll
        for (int q = 0; q < 4; q++) Oa[i][q] = 0.f;

    float m1 = -1e30f, m2 = -1e30f, l1 = 0.f, l2 = 0.f;
    const int rg1 = q0 + w * 16 + (lane >> 2);
    const int rg2 = rg1 + 8;

    const int nkb = 2 * bq + 2;
    for (int j = 0; j < nkb; j++) {
        const int k0g = j * 64;
        const uint32_t skv = sKV0 + (j & 1) * KVSTG_B;

        cp_wait_group<0>();
        __syncthreads();
        if (j + 1 < nkb) {
            const uint32_t skn = sKV0 + ((j + 1) & 1) * KVSTG_B;
#pragma unroll
            for (int i = 0; i < 4; i++) {
                cp_async16(skn + foff[i],           Kcur[i]);
                cp_async16(skn + KTILE_B + foff[i], Vcur[i]);
                Kcur[i] += 64 * KVC; Vcur[i] += 64 * KVC;
            }
            cp_commit();
        }

        const uint32_t sK = skv;
        const uint32_t sV = skv + KTILE_B;

        // --- S = Q K^T in fp16 accumulate ---
        uint32_t Sh[8][2];
#pragma unroll
        for (int t = 0; t < 8; t++) { Sh[t][0] = 0u; Sh[t][1] = 0u; }

#pragma unroll
        for (int kc = 0; kc < 8; kc++) {
            uint32_t af[4];
            ldsm_x4(af, sQ + (uint32_t)((w * 16 + arow) * FROWB + (kc * 16 + akoff) * 2));
#pragma unroll
            for (int np = 0; np < 4; np++) {
                uint32_t bf[4];
                ldsm_x4(bf, sK + (uint32_t)((np * 16 + brow) * FROWB + (kc * 16 + bkoff) * 2));
                mma16816_h(Sh[2 * np],     af, bf);
                mma16816_h(Sh[2 * np + 1], af, bf + 2);
            }
        }

        // unpack fp16 S -> fp32
        float S[8][4];
#pragma unroll
        for (int t = 0; t < 8; t++) {
            float2 lo = __half22float2(*(__half2*)&Sh[t][0]);
            float2 hi = __half22float2(*(__half2*)&Sh[t][1]);
            S[t][0] = lo.x; S[t][1] = lo.y;
            S[t][2] = hi.x; S[t][3] = hi.y;
        }

        // mask + online softmax (exp2 domain; Q carries log2e)
        const bool diag = (k0g + 63 > q0 + w * 16);
        float mx1 = -1e30f, mx2 = -1e30f;
#pragma unroll
        for (int t = 0; t < 8; t++) {
            int cg = k0g + t * 8 + (lane & 3) * 2;
#pragma unroll
            for (int e = 0; e < 2; e++) {
                float s0 = S[t][e];
                float s1 = S[t][2 + e];
                if (diag) {
                    if (cg + e > rg1) s0 = -1e30f;
                    if (cg + e > rg2) s1 = -1e30f;
                }
                S[t][e] = s0;
                S[t][2 + e] = s1;
                mx1 = fmaxf(mx1, s0);
                mx2 = fmaxf(mx2, s1);
            }
        }
        mx1 = fmaxf(mx1, __shfl_xor_sync(0xffffffff, mx1, 1));
        mx1 = fmaxf(mx1, __shfl_xor_sync(0xffffffff, mx1, 2));
        mx2 = fmaxf(mx2, __shfl_xor_sync(0xffffffff, mx2, 1));
        mx2 = fmaxf(mx2, __shfl_xor_sync(0xffffffff, mx2, 2));

        float mn1 = fmaxf(m1, mx1), mn2 = fmaxf(m2, mx2);
        float f1 = exp2f(m1 - mn1), f2 = exp2f(m2 - mn2);
        float rs1 = 0.f, rs2 = 0.f;
#pragma unroll
        for (int t = 0; t < 8; t++) {
#pragma unroll
            for (int e = 0; e < 2; e++) {
                float p0 = exp2f(S[t][e] - mn1);
                float p1 = exp2f(S[t][2 + e] - mn2);
                S[t][e] = p0;
                S[t][2 + e] = p1;
                rs1 += p0;
                rs2 += p1;
            }
        }
        rs1 += __shfl_xor_sync(0xffffffff, rs1, 1);
        rs1 += __shfl_xor_sync(0xffffffff, rs1, 2);
        rs2 += __shfl_xor_sync(0xffffffff, rs2, 1);
        rs2 += __shfl_xor_sync(0xffffffff, rs2, 2);
        l1 = l1 * f1 + rs1;
        l2 = l2 * f2 + rs2;
        m1 = mn1; m2 = mn2;
#pragma unroll
        for (int t = 0; t < 16; t++) {
            Oa[t][0] *= f1; Oa[t][1] *= f1;
            Oa[t][2] *= f2; Oa[t][3] *= f2;
        }

        // --- O += P V (fp32 accumulate) ---
#pragma unroll
        for (int kc = 0; kc < 4; kc++) {
            uint32_t pf[4];
            pf[0] = pack_h2(S[2 * kc][0],     S[2 * kc][1]);
            pf[1] = pack_h2(S[2 * kc][2],     S[2 * kc][3]);
            pf[2] = pack_h2(S[2 * kc + 1][0], S[2 * kc + 1][1]);
            pf[3] = pack_h2(S[2 * kc + 1][2], S[2 * kc + 1][3]);
#pragma unroll
            for (int np = 0; np < 8; np++) {
                uint32_t vf[4];
                ldsm_x4_t(vf, sV + (uint32_t)((kc * 16 + vrow) * FROWB
                                              + (np * 16 + vnoff) * 2));
                mma16816(Oa[2 * np],     pf, vf);
                mma16816(Oa[2 * np + 1], pf, vf + 2);
            }
        }
    }

    const float il1 = 1.f / l1, il2 = 1.f / l2;
    const size_t base1 = ((size_t)b * Tn + q0 + w * 16 + (lane >> 2)) * Cn + h * HD;
    const size_t base2 = base1 + 8 * (size_t)Cn;
#pragma unroll
    for (int nt = 0; nt < 16; nt++) {
        int col = nt * 8 + (lane & 3) * 2;
        *(__half2*)(Yg + base1 + col) =
            __floats2half2_rn(Oa[nt][0] * il1, Oa[nt][1] * il1);
        *(__half2*)(Yg + base2 + col) =
            __floats2half2_rn(Oa[nt][2] * il2, Oa[nt][3] * il2);
    }
}

// ===========================================================================
// launch
// ===========================================================================
extern "C" void kernel_launch(void* const* d_in, const int* in_sizes, int n_in,
                              void* d_out, int out_size)
{
    const float* x   = (const float*)d_in[0];
    const float* Wq  = (const float*)d_in[1];
    const float* Wk  = (const float*)d_in[2];
    const float* Wv  = (const float*)d_in[3];
    const float* Wo  = (const float*)d_in[4];
    const float* fc  = (const float*)d_in[5];
    const float* fs  = (const float*)d_in[6];
    float* out = (float*)d_out;

    __half *X16, *Q16, *K16, *V16, *Y16, *WqT, *WkT, *WvT, *WoT;
    cudaGetSymbolAddress((void**)&X16, g_X16);
    cudaGetSymbolAddress((void**)&Q16, g_Q16);
    cudaGetSymbolAddress((void**)&K16, g_K16);
    cudaGetSymbolAddress((void**)&V16, g_V16);
    cudaGetSymbolAddress((void**)&Y16, g_Y16);
    cudaGetSymbolAddress((void**)&WqT, g_WqT);
    cudaGetSymbolAddress((void**)&WkT, g_WkT);
    cudaGetSymbolAddress((void**)&WvT, g_WvT);
    cudaGetSymbolAddress((void**)&WoT, g_WoT);

    cudaFuncSetAttribute(gemm_qkv,
                         cudaFuncAttributeMaxDynamicSharedMemorySize, GEMM_SMEM);
    cudaFuncSetAttribute(gemm_out,
                         cudaFuncAttributeMaxDynamicSharedMemorySize, GEMM_SMEM);
    cudaFuncSetAttribute(flash_attn_mma,
                         cudaFuncAttributeMaxDynamicSharedMemorySize, FLASH_SMEM);

    // fused prep
    {
        dim3 g(128, 64, 5);
        prep_kernel<<<g, 256>>>(x, Wq, Wk, Wv, Wo, X16, WqT, WkT, WvT, WoT);
    }

    // fused QKV projection (rope + exp2-scale fused into epilogue)
    {
        dim3 g(24, Mrows / 128);      // 24 x 32 = 768 CTAs
        gemm_qkv<<<g, 128, GEMM_SMEM>>>(X16, WqT, WkT, WvT,
                                        Q16, K16, V16, fc, fs);
    }

    // attention (fp16 HMMA flash, S in fp16-acc)
    {
        dim3 g(Tn / 128, NH, Bn);     // 16 x 16 x 2
        flash_attn_mma<<<g, 256, FLASH_SMEM>>>(Q16, K16, V16, Y16);
    }

    // output projection
    {
        dim3 go(Cn / 128, Mrows / 128);   // 16 x 32
        gemm_out<<<go, 128, GEMM_SMEM>>>(Y16, WoT, out, Cn, Cn);
    }
}